// round 2
// baseline (speedup 1.0000x reference)
#include <cuda_runtime.h>
#include <math.h>
#include <stdint.h>

#define Bsz 64
#define Lsz 512
#define Esz 512
#define Hsz 1024
#define NG  4096   // 4*H, gate-interleaved columns: c = h*4+g (g: 0=f,1=i,2=o,3=u)
#define NSPLIT 4
#define NCTA 128   // persistent grid (<=148 SMs -> co-resident)

// Scratch (device globals: allocation-free kernel_launch)
__device__ float g_Xg[(size_t)Lsz * Bsz * NG];   // [t][b][h*4+g]
__device__ float g_Wh[(size_t)Hsz * NG];         // [k][h*4+g]
__device__ float g_part[NSPLIT][Bsz * NG];       // per-step K-split partials

// grid barrier state (self-consistent across launches; monotone gen)
__device__ unsigned g_count = 0;
__device__ volatile unsigned g_gen = 0;

// ---------------------------------------------------------------------------
// packed f32x2 helpers (ptxas never auto-fuses FFMA2; PTX-only)
// ---------------------------------------------------------------------------
__device__ __forceinline__ unsigned long long ffma2(unsigned long long a,
                                                    unsigned long long b,
                                                    unsigned long long c) {
    unsigned long long d;
    asm("fma.rn.f32x2 %0, %1, %2, %3;" : "=l"(d) : "l"(a), "l"(b), "l"(c));
    return d;
}
__device__ __forceinline__ unsigned long long packdup(float x) {
    unsigned long long r;
    asm("mov.b64 %0, {%1, %1};" : "=l"(r) : "f"(x));
    return r;
}
__device__ __forceinline__ float2 unpack2(unsigned long long v) {
    float2 f;
    asm("mov.b64 {%0, %1}, %2;" : "=f"(f.x), "=f"(f.y) : "l"(v));
    return f;
}

__device__ __forceinline__ void grid_sync() {
    __threadfence();
    __syncthreads();
    if (threadIdx.x == 0) {
        unsigned gen = g_gen;
        unsigned prev = atomicAdd(&g_count, 1);
        if (prev == (unsigned)(NCTA - 1)) {
            g_count = 0;
            __threadfence();
            g_gen = gen + 1;
        } else {
            while (g_gen == gen) __nanosleep(32);
        }
    }
    __syncthreads();
}

// ---------------------------------------------------------------------------
// Repack recurrent weights (rows E..D-1) into [k][h*4+g]
// ---------------------------------------------------------------------------
__global__ void pack_wh_kernel(const float* __restrict__ Wf, const float* __restrict__ Wi,
                               const float* __restrict__ Wo, const float* __restrict__ Wu)
{
    int idx = blockIdx.x * 256 + threadIdx.x;
    int k = idx >> 12;
    int c = idx & 4095;
    int h = c >> 2;
    int g = c & 3;
    const float* W = (g == 0) ? Wf : (g == 1) ? Wi : (g == 2) ? Wo : Wu;
    g_Wh[idx] = W[(size_t)(Esz + k) * Hsz + h];
}

// ---------------------------------------------------------------------------
// Phase 1: Xg[t][b][c] = (x @ Wx)[m][c] + bias[c],  m = b*L + t
// 128x128 tile, 256 threads, 8x8 micro-tile via 32 FFMA2/k.
// ---------------------------------------------------------------------------
__global__ __launch_bounds__(256) void gemm_x_kernel(
    const float* __restrict__ x,
    const float* __restrict__ Wf, const float* __restrict__ Wi,
    const float* __restrict__ Wo, const float* __restrict__ Wu,
    const float* __restrict__ bf, const float* __restrict__ bi,
    const float* __restrict__ bo, const float* __restrict__ bu)
{
    __shared__ float As[16][128];
    __shared__ float Bs[16][128];

    const int n0 = blockIdx.x * 128;
    const int m0 = blockIdx.y * 128;
    const int tid = threadIdx.x;
    const int tx = tid & 15, ty = tid >> 4;

    unsigned long long accp[8][4];
#pragma unroll
    for (int r = 0; r < 8; r++)
#pragma unroll
        for (int p = 0; p < 4; p++) accp[r][p] = 0ull;

    const int bn = tid & 127;
    const int bkb = tid >> 7;
    const int bc = n0 + bn;
    const int bh = bc >> 2;
    const int bg = bc & 3;
    const float* Wsel = (bg == 0) ? Wf : (bg == 1) ? Wi : (bg == 2) ? Wo : Wu;

    for (int kt = 0; kt < Esz; kt += 16) {
#pragma unroll
        for (int i = 0; i < 2; i++) {
            int idx = tid + 256 * i;
            int row = idx >> 2, kq = idx & 3;
            float4 av = *(const float4*)(x + (size_t)(m0 + row) * Esz + kt + kq * 4);
            As[kq * 4 + 0][row] = av.x;
            As[kq * 4 + 1][row] = av.y;
            As[kq * 4 + 2][row] = av.z;
            As[kq * 4 + 3][row] = av.w;
        }
#pragma unroll
        for (int kk = 0; kk < 8; kk++) {
            int k = bkb * 8 + kk;
            Bs[k][bn] = Wsel[(size_t)(kt + k) * Hsz + bh];
        }
        __syncthreads();

#pragma unroll
        for (int k = 0; k < 16; k++) {
            float a_reg[8];
            *(float4*)&a_reg[0] = *(const float4*)&As[k][ty * 4];
            *(float4*)&a_reg[4] = *(const float4*)&As[k][64 + ty * 4];
            ulonglong2 bl0 = *(const ulonglong2*)&Bs[k][tx * 4];
            ulonglong2 bl1 = *(const ulonglong2*)&Bs[k][64 + tx * 4];
#pragma unroll
            for (int r = 0; r < 8; r++) {
                unsigned long long ad = packdup(a_reg[r]);
                accp[r][0] = ffma2(ad, bl0.x, accp[r][0]);
                accp[r][1] = ffma2(ad, bl0.y, accp[r][1]);
                accp[r][2] = ffma2(ad, bl1.x, accp[r][2]);
                accp[r][3] = ffma2(ad, bl1.y, accp[r][3]);
            }
        }
        __syncthreads();
    }

    const int hA = (n0 >> 2) + tx;
    const int hB = hA + 16;
    const float4 biasA = make_float4(bf[hA], bi[hA], bo[hA], bu[hA]);
    const float4 biasB = make_float4(bf[hB], bi[hB], bo[hB], bu[hB]);

#pragma unroll
    for (int r = 0; r < 8; r++) {
        int m = m0 + ((r < 4) ? (ty * 4 + r) : (64 + ty * 4 + (r - 4)));
        int b = m >> 9;
        int t = m & 511;
        float* dst = g_Xg + (size_t)(t * Bsz + b) * NG + n0;
        float2 q0 = unpack2(accp[r][0]), q1 = unpack2(accp[r][1]);
        float2 q2 = unpack2(accp[r][2]), q3 = unpack2(accp[r][3]);
        float4 v0 = make_float4(q0.x + biasA.x, q0.y + biasA.y,
                                q1.x + biasA.z, q1.y + biasA.w);
        float4 v1 = make_float4(q2.x + biasB.x, q2.y + biasB.y,
                                q3.x + biasB.z, q3.y + biasB.w);
        *(float4*)(dst + tx * 4) = v0;
        *(float4*)(dst + 64 + tx * 4) = v1;
    }
}

// ---------------------------------------------------------------------------
// Persistent recurrence: 128 CTAs x 256 threads, all 512 steps in one launch.
// Per step: phase A (h_prev @ Wh, K-split 4 -> g_part), barrier,
//           phase B (reduce + gates + cell update, c in registers), barrier.
// ---------------------------------------------------------------------------
__global__ __launch_bounds__(256, 1) void lstm_persist_kernel(
    const float* __restrict__ mask,
    const float* __restrict__ h0, const float* __restrict__ c0,
    float* __restrict__ outh, float* __restrict__ outc)
{
    __shared__ float As[16][64];
    __shared__ float Bs[16][128];

    const int tid = threadIdx.x;
    const int cta = blockIdx.x;
    const int cg = cta & 31;       // col group: cols [cg*128, +128)
    const int ks = cta >> 5;       // K split:  k in [ks*256, +256)
    const int k0 = ks * (Hsz / NSPLIT);
    const int n0 = cg * 128;
    const int tx = tid & 15, ty = tid >> 4;
    const int ar = tid >> 2, akq = tid & 3;
    const int bn = tid & 127, bkb = tid >> 7;

    // phase-B assignment: 2 consecutive h per thread, c resident in regs
    const int e0 = (cta * 256 + tid) * 2;
    const int pb = e0 >> 10;            // batch
    const int ph = e0 & 1023;           // h (even)
    float cA = c0[e0];
    float cB = c0[e0 + 1];

    for (int t = 0; t < Lsz; t++) {
        // ---------------- phase A: partial gates ----------------
        const float* hp = t ? (outh + (size_t)(t - 1) * Hsz) : h0;
        const size_t hstride = t ? (size_t)Lsz * Hsz : (size_t)Hsz;

        unsigned long long accp[4][4];
#pragma unroll
        for (int r = 0; r < 4; r++)
#pragma unroll
            for (int p = 0; p < 4; p++) accp[r][p] = 0ull;

        for (int kt = k0; kt < k0 + (Hsz / NSPLIT); kt += 16) {
            float4 av = *(const float4*)(hp + (size_t)ar * hstride + kt + akq * 4);
            As[akq * 4 + 0][ar] = av.x;
            As[akq * 4 + 1][ar] = av.y;
            As[akq * 4 + 2][ar] = av.z;
            As[akq * 4 + 3][ar] = av.w;
#pragma unroll
            for (int kk = 0; kk < 8; kk++) {
                int k = bkb * 8 + kk;
                Bs[k][bn] = g_Wh[(size_t)(kt + k) * NG + n0 + bn];
            }
            __syncthreads();

#pragma unroll
            for (int k = 0; k < 16; k++) {
                float4 a = *(const float4*)&As[k][ty * 4];
                ulonglong2 bl0 = *(const ulonglong2*)&Bs[k][tx * 4];
                ulonglong2 bl1 = *(const ulonglong2*)&Bs[k][64 + tx * 4];
                float a_reg[4] = {a.x, a.y, a.z, a.w};
#pragma unroll
                for (int r = 0; r < 4; r++) {
                    unsigned long long ad = packdup(a_reg[r]);
                    accp[r][0] = ffma2(ad, bl0.x, accp[r][0]);
                    accp[r][1] = ffma2(ad, bl0.y, accp[r][1]);
                    accp[r][2] = ffma2(ad, bl1.x, accp[r][2]);
                    accp[r][3] = ffma2(ad, bl1.y, accp[r][3]);
                }
            }
            __syncthreads();
        }

#pragma unroll
        for (int r = 0; r < 4; r++) {
            int b = ty * 4 + r;
            float* dst = g_part[ks] + (size_t)b * NG + n0;
            float2 q0 = unpack2(accp[r][0]), q1 = unpack2(accp[r][1]);
            float2 q2 = unpack2(accp[r][2]), q3 = unpack2(accp[r][3]);
            *(float4*)(dst + tx * 4)      = make_float4(q0.x, q0.y, q1.x, q1.y);
            *(float4*)(dst + 64 + tx * 4) = make_float4(q2.x, q2.y, q3.x, q3.y);
        }

        grid_sync();

        // ---------------- phase B: reduce + gates + cell ----------------
        {
            const float* xg = g_Xg + ((size_t)t * Bsz + pb) * NG + (size_t)ph * 4;
            float4 vA = *(const float4*)xg;
            float4 vB = *(const float4*)(xg + 4);
#pragma unroll
            for (int s = 0; s < NSPLIT; s++) {
                const float4* pp = (const float4*)(g_part[s] + (size_t)pb * NG + (size_t)ph * 4);
                float4 a = __ldcg(pp);        // L2-only: addresses reused every step
                float4 b2 = __ldcg(pp + 1);
                vA.x += a.x;  vA.y += a.y;  vA.z += a.z;  vA.w += a.w;
                vB.x += b2.x; vB.y += b2.y; vB.z += b2.z; vB.w += b2.w;
            }
            float m = mask[pb * Lsz + t];

            float f0 = 1.f / (1.f + expf(-vA.x));
            float i0 = 1.f / (1.f + expf(-vA.y));
            float o0 = 1.f / (1.f + expf(-vA.z));
            float u0 = tanhf(vA.w);
            float nc0 = f0 * cA + i0 * u0;
            float nh0 = o0 * tanhf(nc0);
            nh0 *= m; nc0 *= m;

            float f1 = 1.f / (1.f + expf(-vB.x));
            float i1 = 1.f / (1.f + expf(-vB.y));
            float o1 = 1.f / (1.f + expf(-vB.z));
            float u1 = tanhf(vB.w);
            float nc1 = f1 * cB + i1 * u1;
            float nh1 = o1 * tanhf(nc1);
            nh1 *= m; nc1 *= m;

            cA = nc0; cB = nc1;

            size_t oidx = ((size_t)pb * Lsz + t) * Hsz + ph;
            *(float2*)(outh + oidx) = make_float2(nh0, nh1);
            *(float2*)(outc + oidx) = make_float2(nc0, nc1);
        }

        grid_sync();
    }
}

// ---------------------------------------------------------------------------
extern "C" void kernel_launch(void* const* d_in, const int* in_sizes, int n_in,
                              void* d_out, int out_size)
{
    const float* x    = (const float*)d_in[0];
    const float* mask = (const float*)d_in[1];
    const float* Wf   = (const float*)d_in[2];
    const float* bf   = (const float*)d_in[3];
    const float* Wi   = (const float*)d_in[4];
    const float* bi   = (const float*)d_in[5];
    const float* Wo   = (const float*)d_in[6];
    const float* bo   = (const float*)d_in[7];
    const float* Wu   = (const float*)d_in[8];
    const float* bu   = (const float*)d_in[9];
    const float* h0   = (const float*)d_in[10];
    const float* c0   = (const float*)d_in[11];

    float* outh = (float*)d_out;
    float* outc = outh + (size_t)Bsz * Lsz * Hsz;

    pack_wh_kernel<<<(Hsz * NG) / 256, 256>>>(Wf, Wi, Wo, Wu);
    gemm_x_kernel<<<dim3(NG / 128, (Bsz * Lsz) / 128), 256>>>(
        x, Wf, Wi, Wo, Wu, bf, bi, bo, bu);
    lstm_persist_kernel<<<NCTA, 256>>>(mask, h0, c0, outh, outc);
}

// round 3
// speedup vs baseline: 1.1951x; 1.1951x over previous
#include <cuda_runtime.h>
#include <math.h>

#define Bsz 64
#define Lsz 512
#define Esz 512
#define Hsz 1024
#define Dsz 1536
#define NG  4096      // 4*H gate-interleaved: col = h*4+g (0=f,1=i,2=o,3=u)
#define NSPLIT 16
#define NCG 8         // column groups of 512
#define KCH 64        // k-chunk per CTA (Hsz/NSPLIT)
#define NCTA 128

// Device scratch (no allocations allowed)
__device__ float g_Xg[(size_t)Lsz * Bsz * NG];     // [t][b][col]
__device__ float g_Wall[(size_t)Dsz * NG];         // [k][col] gate-interleaved, 24MB
__device__ float g_ball[NG];
__device__ float g_part[NSPLIT][Bsz * NG];         // 16MB
__device__ volatile unsigned g_cntA[NCG];          // partials-done per colgroup (16/step)
__device__ volatile unsigned g_cntB[NCG];          // h-written per colgroup   (16/step)

// ---------------- packed f32x2 helpers ----------------
__device__ __forceinline__ unsigned long long ffma2(unsigned long long a,
                                                    unsigned long long b,
                                                    unsigned long long c) {
    unsigned long long d;
    asm("fma.rn.f32x2 %0, %1, %2, %3;" : "=l"(d) : "l"(a), "l"(b), "l"(c));
    return d;
}
__device__ __forceinline__ unsigned long long packdup(float x) {
    unsigned long long r;
    asm("mov.b64 %0, {%1, %1};" : "=l"(r) : "f"(x));
    return r;
}
__device__ __forceinline__ float2 unpack2(unsigned long long v) {
    float2 f;
    asm("mov.b64 {%0, %1}, %2;" : "=f"(f.x), "=f"(f.y) : "l"(v));
    return f;
}

// ---------------------------------------------------------------------------
// Pack: W_all[k][h*4+g], b_all, and reset flow counters
// ---------------------------------------------------------------------------
__global__ void pack_kernel(const float* __restrict__ Wf, const float* __restrict__ Wi,
                            const float* __restrict__ Wo, const float* __restrict__ Wu,
                            const float* __restrict__ bf, const float* __restrict__ bi,
                            const float* __restrict__ bo, const float* __restrict__ bu)
{
    int idx = blockIdx.x * 256 + threadIdx.x;     // 0 .. Dsz*NG-1
    int k = idx >> 12;
    int c = idx & 4095;
    int h = c >> 2;
    int g = c & 3;
    const float* W = (g == 0) ? Wf : (g == 1) ? Wi : (g == 2) ? Wo : Wu;
    g_Wall[idx] = W[(size_t)k * Hsz + h];
    if (idx < NG) {
        const float* bb = (g == 0) ? bf : (g == 1) ? bi : (g == 2) ? bo : bu;
        g_ball[idx] = bb[h];
    }
    if (idx < NCG) { g_cntA[idx] = 0; g_cntB[idx] = 0; }
}

// ---------------------------------------------------------------------------
// Input projection: Xg[t][b][c] = (x @ Wx)[m][c] + b_all[c], m = b*L + t
// Tile 128(m) x 256(n), K-tile 16, 256 threads, micro 16x8, FFMA2 pairs on m.
// ---------------------------------------------------------------------------
__global__ __launch_bounds__(256) void gemm_x_kernel(const float* __restrict__ x)
{
    __shared__ float As[16][128];
    __shared__ float Bs[16][256];

    const int n0 = blockIdx.x * 256;
    const int m0 = blockIdx.y * 128;
    const int tid = threadIdx.x;
    const int tx = tid & 31, ty = tid >> 5;

    unsigned long long acc[8][8];
#pragma unroll
    for (int rp = 0; rp < 8; rp++)
#pragma unroll
        for (int c = 0; c < 8; c++) acc[rp][c] = 0ull;

    const int arow = tid >> 2, akq = tid & 3;      // A loads: 2/thread (f = tid, tid+256)
    const int arow2 = (tid + 256) >> 2, akq2 = (tid + 256) & 3;

    // preload kt=0
    {
        float4 a0 = *(const float4*)(x + (size_t)(m0 + arow) * Esz + akq * 4);
        float4 a1 = *(const float4*)(x + (size_t)(m0 + arow2) * Esz + akq2 * 4);
        As[akq * 4 + 0][arow] = a0.x; As[akq * 4 + 1][arow] = a0.y;
        As[akq * 4 + 2][arow] = a0.z; As[akq * 4 + 3][arow] = a0.w;
        As[akq2 * 4 + 0][arow2] = a1.x; As[akq2 * 4 + 1][arow2] = a1.y;
        As[akq2 * 4 + 2][arow2] = a1.z; As[akq2 * 4 + 3][arow2] = a1.w;
#pragma unroll
        for (int i = 0; i < 4; i++) {
            int f = tid + 256 * i;
            int k = f >> 6, c4 = f & 63;
            *(float4*)&Bs[k][c4 * 4] = *(const float4*)(g_Wall + (size_t)k * NG + n0 + c4 * 4);
        }
    }
    __syncthreads();

    for (int kt = 0; kt < Esz; kt += 16) {
        // prefetch next tile into registers
        float4 pa0, pa1, pb[4];
        if (kt + 16 < Esz) {
            int ktn = kt + 16;
            pa0 = *(const float4*)(x + (size_t)(m0 + arow) * Esz + ktn + akq * 4);
            pa1 = *(const float4*)(x + (size_t)(m0 + arow2) * Esz + ktn + akq2 * 4);
#pragma unroll
            for (int i = 0; i < 4; i++) {
                int f = tid + 256 * i;
                int k = f >> 6, c4 = f & 63;
                pb[i] = *(const float4*)(g_Wall + (size_t)(ktn + k) * NG + n0 + c4 * 4);
            }
        }

#pragma unroll
        for (int k = 0; k < 16; k++) {
            unsigned long long a_p[8];
#pragma unroll
            for (int rb = 0; rb < 4; rb++) {
                ulonglong2 av = *(const ulonglong2*)&As[k][32 * rb + ty * 4];
                a_p[rb * 2 + 0] = av.x;
                a_p[rb * 2 + 1] = av.y;
            }
            float4 b0 = *(const float4*)&Bs[k][tx * 4];
            float4 b1 = *(const float4*)&Bs[k][128 + tx * 4];
            unsigned long long bd[8] = {packdup(b0.x), packdup(b0.y), packdup(b0.z), packdup(b0.w),
                                        packdup(b1.x), packdup(b1.y), packdup(b1.z), packdup(b1.w)};
#pragma unroll
            for (int rp = 0; rp < 8; rp++)
#pragma unroll
                for (int c = 0; c < 8; c++)
                    acc[rp][c] = ffma2(a_p[rp], bd[c], acc[rp][c]);
        }
        __syncthreads();
        if (kt + 16 < Esz) {
            As[akq * 4 + 0][arow] = pa0.x; As[akq * 4 + 1][arow] = pa0.y;
            As[akq * 4 + 2][arow] = pa0.z; As[akq * 4 + 3][arow] = pa0.w;
            As[akq2 * 4 + 0][arow2] = pa1.x; As[akq2 * 4 + 1][arow2] = pa1.y;
            As[akq2 * 4 + 2][arow2] = pa1.z; As[akq2 * 4 + 3][arow2] = pa1.w;
#pragma unroll
            for (int i = 0; i < 4; i++) {
                int f = tid + 256 * i;
                int k = f >> 6, c4 = f & 63;
                *(float4*)&Bs[k][c4 * 4] = pb[i];
            }
            __syncthreads();
        }
    }

    float4 bias0 = *(const float4*)(g_ball + n0 + tx * 4);
    float4 bias1 = *(const float4*)(g_ball + n0 + 128 + tx * 4);

#pragma unroll
    for (int rp = 0; rp < 8; rp++) {
        float2 q[8];
#pragma unroll
        for (int c = 0; c < 8; c++) q[c] = unpack2(acc[rp][c]);
        int row0 = m0 + 32 * (rp >> 1) + ty * 4 + (rp & 1) * 2;
#pragma unroll
        for (int pr = 0; pr < 2; pr++) {
            int m = row0 + pr;
            int b = m >> 9;
            int t = m & 511;
            float* dst = g_Xg + ((size_t)(t * Bsz + b)) * NG + n0;
            float4 v0, v1;
            if (pr == 0) {
                v0 = make_float4(q[0].x + bias0.x, q[1].x + bias0.y, q[2].x + bias0.z, q[3].x + bias0.w);
                v1 = make_float4(q[4].x + bias1.x, q[5].x + bias1.y, q[6].x + bias1.z, q[7].x + bias1.w);
            } else {
                v0 = make_float4(q[0].y + bias0.x, q[1].y + bias0.y, q[2].y + bias0.z, q[3].y + bias0.w);
                v1 = make_float4(q[4].y + bias1.x, q[5].y + bias1.y, q[6].y + bias1.z, q[7].y + bias1.w);
            }
            *(float4*)(dst + tx * 4) = v0;
            *(float4*)(dst + 128 + tx * 4) = v1;
        }
    }
}

// ---------------------------------------------------------------------------
// Persistent recurrence. CTA (cg,ks): cg = blockIdx/16 (512 cols), ks = k-split.
// Phase A: partial = h(t-1)[:, k0:k0+64] @ Wh[k0:k0+64, cols] (16x8 micro, FFMA2)
// Phase B: CTA owns 8 h-cols x 64 b; c register-resident.
// Sync: per-colgroup monotone counters (dataflow, no global barrier).
// ---------------------------------------------------------------------------
__global__ __launch_bounds__(256, 1) void lstm_persist_kernel(
    const float* __restrict__ mask,
    const float* __restrict__ h0, const float* __restrict__ c0,
    float* __restrict__ outh, float* __restrict__ outc)
{
    __shared__ float As[16][64];
    __shared__ float Bs[16][512];

    const int tid = threadIdx.x;
    const int cg = blockIdx.x >> 4;
    const int ks = blockIdx.x & 15;
    const int k0 = ks * KCH;
    const int n0 = cg * 512;
    const int cgp = ks >> 1;                 // producer colgroup of our h inputs
    const int tx = tid & 63, ty = tid >> 6;
    const int arow = tid >> 2, akq = tid & 3;

    const float* Wh = g_Wall + (size_t)Esz * NG;

    // phase-B ownership: 2 adjacent h per thread, fixed forever -> c in regs
    const int hbase = cg * 128 + ks * 8;
    const int flat = tid * 2;
    const int pb = flat >> 3;
    const int ph = hbase + (flat & 7);
    float cA = c0[pb * Hsz + ph];
    float cB = c0[pb * Hsz + ph + 1];

    for (int t = 0; t < Lsz; t++) {
        // wait: h(t-1) from producer colgroup ready; our g_part cols free to overwrite
        if (tid == 0) {
            unsigned tgt = 16u * (unsigned)t;
            while (g_cntB[cgp] < tgt) __nanosleep(32);
            while (g_cntB[cg] < tgt) __nanosleep(32);
            __threadfence();
        }
        __syncthreads();

        const float* hp = t ? (outh + (size_t)(t - 1) * Hsz) : h0;
        const size_t hstride = t ? (size_t)Lsz * Hsz : (size_t)Hsz;

        unsigned long long acc[8][8];
#pragma unroll
        for (int rp = 0; rp < 8; rp++)
#pragma unroll
            for (int c = 0; c < 8; c++) acc[rp][c] = 0ull;

        // preload kt = k0
        {
            float4 av = *(const float4*)(hp + (size_t)arow * hstride + k0 + akq * 4);
            As[akq * 4 + 0][arow] = av.x; As[akq * 4 + 1][arow] = av.y;
            As[akq * 4 + 2][arow] = av.z; As[akq * 4 + 3][arow] = av.w;
#pragma unroll
            for (int i = 0; i < 8; i++) {
                int f = tid + 256 * i;
                int k = f >> 7, c4 = f & 127;
                *(float4*)&Bs[k][c4 * 4] = *(const float4*)(Wh + (size_t)(k0 + k) * NG + n0 + c4 * 4);
            }
        }
        __syncthreads();

#pragma unroll
        for (int kti = 0; kti < 4; kti++) {
            float4 pa;
            float4 pbuf[8];
            if (kti < 3) {
                int ktn = k0 + (kti + 1) * 16;
                pa = *(const float4*)(hp + (size_t)arow * hstride + ktn + akq * 4);
#pragma unroll
                for (int i = 0; i < 8; i++) {
                    int f = tid + 256 * i;
                    int k = f >> 7, c4 = f & 127;
                    pbuf[i] = *(const float4*)(Wh + (size_t)(ktn + k) * NG + n0 + c4 * 4);
                }
            }

#pragma unroll
            for (int k = 0; k < 16; k++) {
                unsigned long long a_p[8];
#pragma unroll
                for (int rb = 0; rb < 4; rb++) {
                    ulonglong2 av = *(const ulonglong2*)&As[k][16 * rb + ty * 4];
                    a_p[rb * 2 + 0] = av.x;
                    a_p[rb * 2 + 1] = av.y;
                }
                float4 b0 = *(const float4*)&Bs[k][tx * 4];
                float4 b1 = *(const float4*)&Bs[k][256 + tx * 4];
                unsigned long long bd[8] = {packdup(b0.x), packdup(b0.y), packdup(b0.z), packdup(b0.w),
                                            packdup(b1.x), packdup(b1.y), packdup(b1.z), packdup(b1.w)};
#pragma unroll
                for (int rp = 0; rp < 8; rp++)
#pragma unroll
                    for (int c = 0; c < 8; c++)
                        acc[rp][c] = ffma2(a_p[rp], bd[c], acc[rp][c]);
            }
            __syncthreads();
            if (kti < 3) {
                As[akq * 4 + 0][arow] = pa.x; As[akq * 4 + 1][arow] = pa.y;
                As[akq * 4 + 2][arow] = pa.z; As[akq * 4 + 3][arow] = pa.w;
#pragma unroll
                for (int i = 0; i < 8; i++) {
                    int f = tid + 256 * i;
                    int k = f >> 7, c4 = f & 127;
                    *(float4*)&Bs[k][c4 * 4] = pbuf[i];
                }
                __syncthreads();
            }
        }

        // write partials
#pragma unroll
        for (int rp = 0; rp < 8; rp++) {
            float2 q[8];
#pragma unroll
            for (int c = 0; c < 8; c++) q[c] = unpack2(acc[rp][c]);
            int b0r = 16 * (rp >> 1) + ty * 4 + (rp & 1) * 2;
            float* base0 = g_part[ks] + (size_t)b0r * NG + n0;
            *(float4*)(base0 + tx * 4)       = make_float4(q[0].x, q[1].x, q[2].x, q[3].x);
            *(float4*)(base0 + 256 + tx * 4) = make_float4(q[4].x, q[5].x, q[6].x, q[7].x);
            float* base1 = base0 + NG;
            *(float4*)(base1 + tx * 4)       = make_float4(q[0].y, q[1].y, q[2].y, q[3].y);
            *(float4*)(base1 + 256 + tx * 4) = make_float4(q[4].y, q[5].y, q[6].y, q[7].y);
        }
        __threadfence();
        __syncthreads();
        if (tid == 0) {
            atomicAdd((unsigned*)&g_cntA[cg], 1u);
            // wait all 16 partials for our colgroup
            unsigned tgt = 16u * (unsigned)(t + 1);
            while (g_cntA[cg] < tgt) __nanosleep(32);
            __threadfence();
        }
        __syncthreads();

        // ---------------- phase B ----------------
        {
            const float* xg = g_Xg + ((size_t)t * Bsz + pb) * NG + (size_t)ph * 4;
            float4 vA = *(const float4*)xg;
            float4 vB = *(const float4*)(xg + 4);
#pragma unroll
            for (int s = 0; s < NSPLIT; s++) {
                const float4* pp = (const float4*)(g_part[s] + (size_t)pb * NG + (size_t)ph * 4);
                float4 a  = __ldcg(pp);      // must bypass L1: rewritten every step by other SMs
                float4 b2 = __ldcg(pp + 1);
                vA.x += a.x;  vA.y += a.y;  vA.z += a.z;  vA.w += a.w;
                vB.x += b2.x; vB.y += b2.y; vB.z += b2.z; vB.w += b2.w;
            }
            float m = mask[pb * Lsz + t];

            float f0 = 1.f / (1.f + expf(-vA.x));
            float i0 = 1.f / (1.f + expf(-vA.y));
            float o0 = 1.f / (1.f + expf(-vA.z));
            float u0 = tanhf(vA.w);
            float nc0 = f0 * cA + i0 * u0;
            float nh0 = o0 * tanhf(nc0);
            nh0 *= m; nc0 *= m;

            float f1 = 1.f / (1.f + expf(-vB.x));
            float i1 = 1.f / (1.f + expf(-vB.y));
            float o1 = 1.f / (1.f + expf(-vB.z));
            float u1 = tanhf(vB.w);
            float nc1 = f1 * cB + i1 * u1;
            float nh1 = o1 * tanhf(nc1);
            nh1 *= m; nc1 *= m;

            cA = nc0; cB = nc1;

            size_t oidx = ((size_t)pb * Lsz + t) * Hsz + ph;
            *(float2*)(outh + oidx) = make_float2(nh0, nh1);
            *(float2*)(outc + oidx) = make_float2(nc0, nc1);
        }
        __threadfence();
        __syncthreads();
        if (tid == 0) atomicAdd((unsigned*)&g_cntB[cg], 1u);
    }
}

// ---------------------------------------------------------------------------
extern "C" void kernel_launch(void* const* d_in, const int* in_sizes, int n_in,
                              void* d_out, int out_size)
{
    const float* x    = (const float*)d_in[0];
    const float* mask = (const float*)d_in[1];
    const float* Wf   = (const float*)d_in[2];
    const float* bf   = (const float*)d_in[3];
    const float* Wi   = (const float*)d_in[4];
    const float* bi   = (const float*)d_in[5];
    const float* Wo   = (const float*)d_in[6];
    const float* bo   = (const float*)d_in[7];
    const float* Wu   = (const float*)d_in[8];
    const float* bu   = (const float*)d_in[9];
    const float* h0   = (const float*)d_in[10];
    const float* c0   = (const float*)d_in[11];

    float* outh = (float*)d_out;
    float* outc = outh + (size_t)Bsz * Lsz * Hsz;

    pack_kernel<<<(Dsz * NG) / 256, 256>>>(Wf, Wi, Wo, Wu, bf, bi, bo, bu);
    gemm_x_kernel<<<dim3(NG / 256, (Bsz * Lsz) / 128), 256>>>(x);
    lstm_persist_kernel<<<NCTA, 256>>>(mask, h0, c0, outh, outc);
}